// round 7
// baseline (speedup 1.0000x reference)
#include <cuda_runtime.h>
#include <cstdint>
#include <cstddef>

// out[b,i,j] = W[words[b,i], words[b,j]]  (+ root[words[b,i]] when i==j)
// V=10000, B=8, N=2048
//
// R7: multi-CTA prepass bins items per row AND appends first-seen rows to a
// compact worklist (no scan). Main kernel: producer warp grabs 8 compact rows
// per cursor atomic with metadata prefetched one chunk ahead (atomic latency
// hidden behind TMA issues); 5-deep TMA ring of 40KB W rows; 16 consumer
// warps gather+store. Producer resets d_cnt per issued row; CTAs reset
// d_nrows on exit -> graph-replay safe with no extra launches.

#define V 10000
#define B_DIM 8
#define N_DIM 2048
#define NITEMS (B_DIM * N_DIM)     // 16384
#define ROW_BYTES (V * 4)          // 40000
#define NSLOTS 5
#define CONSUMERS 512
#define THREADS (CONSUMERS + 32)
#define GRID_MAIN 152
#define CAP 64                     // max items per row (actual max ~12)
#define CHUNK 8                    // compact rows per cursor grab

__device__ int d_cnt[V];           // zero-init; producer re-zeros issued rows
__device__ int d_rows[V];          // compact list of nonempty rows
__device__ int d_items[V * CAP];
__device__ int d_nrows;            // reset to 0 by main kernel on exit
__device__ int d_wcursor;          // reset to 0 by place_kernel

// ================= prepass: count + place + compact-append =================
__global__ void place_kernel(const int* __restrict__ words)
{
    int k = blockIdx.x * blockDim.x + threadIdx.x;
    if (k == 0) d_wcursor = 0;         // reset main-kernel cursor each replay
    if (k < NITEMS) {
        int r = __ldg(words + k);
        int pos = atomicAdd(&d_cnt[r], 1);
        if (pos < CAP) d_items[r * CAP + pos] = k;
        if (pos == 0) {
            int idx = atomicAdd(&d_nrows, 1);
            d_rows[idx] = r;
        }
    }
}

// ================= mbarrier / TMA helpers =================
__device__ __forceinline__ void mbar_init(uint32_t mbar, uint32_t count) {
    asm volatile("mbarrier.init.shared.b64 [%0], %1;" :: "r"(mbar), "r"(count) : "memory");
}
__device__ __forceinline__ void mbar_expect_tx(uint32_t mbar, uint32_t bytes) {
    asm volatile("mbarrier.arrive.expect_tx.shared.b64 _, [%0], %1;"
                 :: "r"(mbar), "r"(bytes) : "memory");
}
__device__ __forceinline__ void mbar_arrive(uint32_t mbar) {
    asm volatile("mbarrier.arrive.shared.b64 _, [%0];" :: "r"(mbar) : "memory");
}
__device__ __forceinline__ void bulk_copy_g2s(uint32_t dst_smem, const void* src,
                                              uint32_t bytes, uint32_t mbar) {
    asm volatile("cp.async.bulk.shared::cta.global.mbarrier::complete_tx::bytes "
                 "[%0], [%1], %2, [%3];"
                 :: "r"(dst_smem), "l"(src), "r"(bytes), "r"(mbar) : "memory");
}
__device__ __forceinline__ void mbar_wait(uint32_t mbar, uint32_t phase) {
    asm volatile(
        "{\n\t"
        ".reg .pred P;\n\t"
        "WAIT_%=:\n\t"
        "mbarrier.try_wait.parity.acquire.cta.shared::cta.b64 P, [%0], %1, 0x989680;\n\t"
        "@P bra DONE_%=;\n\t"
        "bra WAIT_%=;\n\t"
        "DONE_%=:\n\t"
        "}"
        :: "r"(mbar), "r"(phase) : "memory");
}

// ================= main kernel =================
__global__ __launch_bounds__(THREADS) void pair_gather_ws_kernel(
    const int* __restrict__ words,
    const float* __restrict__ W,
    const float* __restrict__ root,
    float* __restrict__ out)
{
    extern __shared__ float sbuf[];   // NSLOTS * V floats, then barriers
    __shared__ int s_mr[NSLOTS], s_mb[NSLOTS], s_me[NSLOTS];

    const int t = threadIdx.x;
    const uint32_t smem_base = (uint32_t)__cvta_generic_to_shared(sbuf);
    const uint32_t bar_base  = smem_base + NSLOTS * ROW_BYTES;
    // full[s] = bar_base + s*16, empty[s] = bar_base + s*16 + 8

    if (t == 0) {
        #pragma unroll
        for (int s0 = 0; s0 < NSLOTS; ++s0) {
            mbar_init(bar_base + s0 * 16, 1);       // full: producer arrives
            mbar_init(bar_base + s0 * 16 + 8, 1);   // empty: one consumer arrives
        }
    }
    __syncthreads();

    if (t >= CONSUMERS) {
        // ---------------- producer warp ----------------
        const int lane = t - CONSUMERS;
        if (lane == 0)
            asm volatile("fence.proxy.async.shared::cta;" ::: "memory");
        __syncwarp();

        const int nrows = *((volatile int*)&d_nrows);  // snapshot (final after prepass)

        // initial grab + metadata load
        int base;
        if (lane == 0) base = atomicAdd(&d_wcursor, CHUNK);
        base = __shfl_sync(0xFFFFFFFF, base, 0);
        int myr = -1, myc = 0;
        if (base < nrows && lane < CHUNK && base + lane < nrows) {
            myr = __ldg(d_rows + base + lane);
            myc = __ldg(d_cnt + myr);
            if (myc > CAP) myc = CAP;
        }

        int k = 0;   // issued-slot counter (drives slot & phase)
        while (base < nrows) {
            // prefetch next chunk (latency hidden behind current issues)
            int nbase;
            if (lane == 0) nbase = atomicAdd(&d_wcursor, CHUNK);
            nbase = __shfl_sync(0xFFFFFFFF, nbase, 0);
            int nr = -1, nc = 0;
            if (nbase < nrows && lane < CHUNK && nbase + lane < nrows) {
                nr = __ldg(d_rows + nbase + lane);
                nc = __ldg(d_cnt + nr);
                if (nc > CAP) nc = CAP;
            }

            // issue current chunk
            const int lim = (nrows - base < CHUNK) ? (nrows - base) : CHUNK;
            for (int q = 0; q < lim; ++q) {
                const int r = __shfl_sync(0xFFFFFFFF, myr, q);
                const int c = __shfl_sync(0xFFFFFFFF, myc, q);
                const int slot = k % NSLOTS;
                const int n    = k / NSLOTS;
                ++k;
                if (lane == 0) {
                    mbar_wait(bar_base + slot * 16 + 8, (unsigned)((n & 1) ^ 1));
                    s_mr[slot] = r;
                    s_mb[slot] = r * CAP;
                    s_me[slot] = r * CAP + c;
                    d_cnt[r] = 0;                       // replay reset
                    mbar_expect_tx(bar_base + slot * 16, ROW_BYTES);
                    bulk_copy_g2s(smem_base + slot * ROW_BYTES,
                                  W + (size_t)r * V, ROW_BYTES,
                                  bar_base + slot * 16);
                }
            }

            base = nbase; myr = nr; myc = nc;
        }

        // sentinel
        if (lane == 0) {
            const int slot = k % NSLOTS;
            const int n    = k / NSLOTS;
            mbar_wait(bar_base + slot * 16 + 8, (unsigned)((n & 1) ^ 1));
            s_mr[slot] = -1;
            mbar_arrive(bar_base + slot * 16);
            d_nrows = 0;   // replay reset; safe: cursor already exhausted
        }
    } else {
        // ---------------- consumer warps ----------------
        for (int k = 0;; ++k) {
            const int slot = k % NSLOTS;
            const int n    = k / NSLOTS;
            mbar_wait(bar_base + slot * 16, (unsigned)(n & 1));

            const int r = s_mr[slot];
            if (r < 0) break;
            const int b = s_mb[slot];
            const int e = s_me[slot];
            const float rootv = __ldg(root + r);
            const float* __restrict__ row = sbuf + (size_t)slot * V;

            for (int it = b; it < e; ++it) {
                const int blk = __ldg(d_items + it);   // b*N + i
                const int bb  = blk >> 11;
                const int i   = blk & (N_DIM - 1);
                const int4 c  = __ldg(reinterpret_cast<const int4*>(
                                         words + (size_t)bb * N_DIM) + t);
                const int j0 = t * 4;
                float4 v;
                v.x = row[c.x];
                v.y = row[c.y];
                v.z = row[c.z];
                v.w = row[c.w];
                const unsigned d = (unsigned)(i - j0);
                if (d < 4u) {
                    if      (d == 0u) v.x += rootv;
                    else if (d == 1u) v.y += rootv;
                    else if (d == 2u) v.z += rootv;
                    else              v.w += rootv;
                }
                *reinterpret_cast<float4*>(out + (size_t)blk * N_DIM + j0) = v;
            }

            asm volatile("bar.sync 1, %0;" :: "n"(CONSUMERS) : "memory");
            if (t == 0) mbar_arrive(bar_base + slot * 16 + 8);
        }
    }
}

// ================= launch =================
extern "C" void kernel_launch(void* const* d_in, const int* in_sizes, int n_in,
                              void* d_out, int out_size)
{
    const int*   words = (const int*)  d_in[0];
    const float* W     = (const float*)d_in[1];
    const float* root  = (const float*)d_in[2];
    float*       out   = (float*)d_out;

    static const size_t SMEM_DYN = (size_t)NSLOTS * ROW_BYTES + NSLOTS * 16;
    cudaFuncSetAttribute(pair_gather_ws_kernel,
                         cudaFuncAttributeMaxDynamicSharedMemorySize,
                         (int)SMEM_DYN);

    place_kernel<<<(NITEMS + 255) / 256, 256>>>(words);
    pair_gather_ws_kernel<<<GRID_MAIN, THREADS, SMEM_DYN>>>(words, W, root, out);
}

// round 8
// speedup vs baseline: 1.0190x; 1.0190x over previous
#include <cuda_runtime.h>
#include <cstdint>
#include <cstddef>

// out[b,i,j] = W[words[b,i], words[b,j]]  (+ root[words[b,i]] when i==j)
// V=10000, B=8, N=2048
//
// R8: sorted row issue order (walk vocab ids like R6) combined with the
// software-pipelined producer (prefetch next chunk like R7). Prepass: one
// multi-CTA kernel binning items per row. Producer: grabs 4 vocab ids per
// cursor atomic, atomicExch read-and-resets counts one chunk AHEAD of issue
// so the dependent atomic chain hides behind TMA slot issues; consecutive
// ids -> contiguous W streaming. 5-deep TMA ring; 16 consumer warps.

#define V 10000
#define B_DIM 8
#define N_DIM 2048
#define NITEMS (B_DIM * N_DIM)     // 16384
#define ROW_BYTES (V * 4)          // 40000
#define NSLOTS 5
#define CONSUMERS 512
#define THREADS (CONSUMERS + 32)
#define GRID_MAIN 152
#define CAP 64                     // max items per row (actual max ~12)
#define CHUNK 4                    // vocab ids per cursor grab (2500 chunks)

__device__ int d_cnt[V];           // zero-init; producer exchanges back to 0
__device__ int d_items[V * CAP];
__device__ int d_wcursor;          // reset by place_kernel

// ================= prepass: count + place =================
__global__ void place_kernel(const int* __restrict__ words)
{
    int k = blockIdx.x * blockDim.x + threadIdx.x;
    if (k == 0) d_wcursor = 0;         // reset main-kernel cursor each replay
    if (k < NITEMS) {
        int r = __ldg(words + k);
        int pos = atomicAdd(&d_cnt[r], 1);
        if (pos < CAP) d_items[r * CAP + pos] = k;
    }
}

// ================= mbarrier / TMA helpers =================
__device__ __forceinline__ void mbar_init(uint32_t mbar, uint32_t count) {
    asm volatile("mbarrier.init.shared.b64 [%0], %1;" :: "r"(mbar), "r"(count) : "memory");
}
__device__ __forceinline__ void mbar_expect_tx(uint32_t mbar, uint32_t bytes) {
    asm volatile("mbarrier.arrive.expect_tx.shared.b64 _, [%0], %1;"
                 :: "r"(mbar), "r"(bytes) : "memory");
}
__device__ __forceinline__ void mbar_arrive(uint32_t mbar) {
    asm volatile("mbarrier.arrive.shared.b64 _, [%0];" :: "r"(mbar) : "memory");
}
__device__ __forceinline__ void bulk_copy_g2s(uint32_t dst_smem, const void* src,
                                              uint32_t bytes, uint32_t mbar) {
    asm volatile("cp.async.bulk.shared::cta.global.mbarrier::complete_tx::bytes "
                 "[%0], [%1], %2, [%3];"
                 :: "r"(dst_smem), "l"(src), "r"(bytes), "r"(mbar) : "memory");
}
__device__ __forceinline__ void mbar_wait(uint32_t mbar, uint32_t phase) {
    asm volatile(
        "{\n\t"
        ".reg .pred P;\n\t"
        "WAIT_%=:\n\t"
        "mbarrier.try_wait.parity.acquire.cta.shared::cta.b64 P, [%0], %1, 0x989680;\n\t"
        "@P bra DONE_%=;\n\t"
        "bra WAIT_%=;\n\t"
        "DONE_%=:\n\t"
        "}"
        :: "r"(mbar), "r"(phase) : "memory");
}

// ================= main kernel =================
__global__ __launch_bounds__(THREADS) void pair_gather_ws_kernel(
    const int* __restrict__ words,
    const float* __restrict__ W,
    const float* __restrict__ root,
    float* __restrict__ out)
{
    extern __shared__ float sbuf[];   // NSLOTS * V floats, then barriers
    __shared__ int s_mr[NSLOTS], s_mb[NSLOTS], s_me[NSLOTS];

    const int t = threadIdx.x;
    const uint32_t smem_base = (uint32_t)__cvta_generic_to_shared(sbuf);
    const uint32_t bar_base  = smem_base + NSLOTS * ROW_BYTES;
    // full[s] = bar_base + s*16, empty[s] = bar_base + s*16 + 8

    if (t == 0) {
        #pragma unroll
        for (int s0 = 0; s0 < NSLOTS; ++s0) {
            mbar_init(bar_base + s0 * 16, 1);       // full: producer arrives
            mbar_init(bar_base + s0 * 16 + 8, 1);   // empty: one consumer arrives
        }
    }
    __syncthreads();

    if (t >= CONSUMERS) {
        // ---------------- producer warp ----------------
        const int lane = t - CONSUMERS;
        if (lane == 0)
            asm volatile("fence.proxy.async.shared::cta;" ::: "memory");
        __syncwarp();

        // prologue: grab first chunk + exchange its counts
        int base;
        if (lane == 0) base = atomicAdd(&d_wcursor, CHUNK);
        base = __shfl_sync(0xFFFFFFFF, base, 0);
        int myc = 0;
        if (base < V && lane < CHUNK && base + lane < V) {
            myc = atomicExch(&d_cnt[base + lane], 0);   // read + reset
            if (myc > CAP) myc = CAP;
        }

        int k = 0;   // issued-slot counter (drives slot & phase)
        while (base < V) {
            // prefetch NEXT chunk (cursor atomic + exchanges) before issuing
            // the current one: latency hides behind the TMA slot issues below
            int nbase;
            if (lane == 0) nbase = atomicAdd(&d_wcursor, CHUNK);
            nbase = __shfl_sync(0xFFFFFFFF, nbase, 0);
            int nc = 0;
            if (nbase < V && lane < CHUNK && nbase + lane < V) {
                nc = atomicExch(&d_cnt[nbase + lane], 0);
                if (nc > CAP) nc = CAP;
            }

            // issue current chunk (sorted ids -> contiguous W rows)
            unsigned mask = __ballot_sync(0xFFFFFFFF, myc > 0);
            while (mask) {
                const int src = __ffs(mask) - 1;
                mask &= mask - 1;
                const int r = base + src;
                const int c = __shfl_sync(0xFFFFFFFF, myc, src);

                const int slot = k % NSLOTS;
                const int n    = k / NSLOTS;
                ++k;
                if (lane == 0) {
                    mbar_wait(bar_base + slot * 16 + 8, (unsigned)((n & 1) ^ 1));
                    s_mr[slot] = r;
                    s_mb[slot] = r * CAP;
                    s_me[slot] = r * CAP + c;
                    mbar_expect_tx(bar_base + slot * 16, ROW_BYTES);
                    bulk_copy_g2s(smem_base + slot * ROW_BYTES,
                                  W + (size_t)r * V, ROW_BYTES,
                                  bar_base + slot * 16);
                }
            }

            base = nbase; myc = nc;
        }

        // sentinel
        if (lane == 0) {
            const int slot = k % NSLOTS;
            const int n    = k / NSLOTS;
            mbar_wait(bar_base + slot * 16 + 8, (unsigned)((n & 1) ^ 1));
            s_mr[slot] = -1;
            mbar_arrive(bar_base + slot * 16);
        }
    } else {
        // ---------------- consumer warps ----------------
        for (int k = 0;; ++k) {
            const int slot = k % NSLOTS;
            const int n    = k / NSLOTS;
            mbar_wait(bar_base + slot * 16, (unsigned)(n & 1));

            const int r = s_mr[slot];
            if (r < 0) break;
            const int b = s_mb[slot];
            const int e = s_me[slot];
            const float rootv = __ldg(root + r);
            const float* __restrict__ row = sbuf + (size_t)slot * V;

            for (int it = b; it < e; ++it) {
                const int blk = __ldg(d_items + it);   // b*N + i
                const int bb  = blk >> 11;
                const int i   = blk & (N_DIM - 1);
                const int4 c  = __ldg(reinterpret_cast<const int4*>(
                                         words + (size_t)bb * N_DIM) + t);
                const int j0 = t * 4;
                float4 v;
                v.x = row[c.x];
                v.y = row[c.y];
                v.z = row[c.z];
                v.w = row[c.w];
                const unsigned d = (unsigned)(i - j0);
                if (d < 4u) {
                    if      (d == 0u) v.x += rootv;
                    else if (d == 1u) v.y += rootv;
                    else if (d == 2u) v.z += rootv;
                    else              v.w += rootv;
                }
                *reinterpret_cast<float4*>(out + (size_t)blk * N_DIM + j0) = v;
            }

            asm volatile("bar.sync 1, %0;" :: "n"(CONSUMERS) : "memory");
            if (t == 0) mbar_arrive(bar_base + slot * 16 + 8);
        }
    }
}

// ================= launch =================
extern "C" void kernel_launch(void* const* d_in, const int* in_sizes, int n_in,
                              void* d_out, int out_size)
{
    const int*   words = (const int*)  d_in[0];
    const float* W     = (const float*)d_in[1];
    const float* root  = (const float*)d_in[2];
    float*       out   = (float*)d_out;

    static const size_t SMEM_DYN = (size_t)NSLOTS * ROW_BYTES + NSLOTS * 16;
    cudaFuncSetAttribute(pair_gather_ws_kernel,
                         cudaFuncAttributeMaxDynamicSharedMemorySize,
                         (int)SMEM_DYN);

    place_kernel<<<(NITEMS + 255) / 256, 256>>>(words);
    pair_gather_ws_kernel<<<GRID_MAIN, THREADS, SMEM_DYN>>>(words, W, root, out);
}

// round 9
// speedup vs baseline: 1.1952x; 1.1730x over previous
#include <cuda_runtime.h>
#include <cstdint>
#include <cstddef>

// out[b,i,j] = W[words[b,i], words[b,j]]  (+ root[words[b,i]] when i==j)
// V=10000, B=8, N=2048
//
// R9: R8 + item lists delivered through smem. The producer warp prefetches
// each row's item indices from the strided gmem bins one chunk ahead (lanes
// 8q..8q+7 hold row q's items) and writes them into s_items[slot] at issue
// time, so consumers never take the cold DRAM broadcast miss on d_items
// inside the slot-hold window. Rows with >8 items (P~5e-5) fall back to gmem.

#define V 10000
#define B_DIM 8
#define N_DIM 2048
#define NITEMS (B_DIM * N_DIM)     // 16384
#define ROW_BYTES (V * 4)          // 40000
#define NSLOTS 5
#define CONSUMERS 512
#define THREADS (CONSUMERS + 32)
#define GRID_MAIN 152
#define CAP 64                     // bin capacity (actual max ~12)
#define CHUNK 4                    // vocab ids per cursor grab (2500 chunks)
#define SITEMS 8                   // items carried via smem per row

__device__ int d_cnt[V];           // zero-init; producer exchanges back to 0
__device__ int d_items[V * CAP];
__device__ int d_wcursor;          // reset by place_kernel

// ================= prepass: count + place =================
__global__ void place_kernel(const int* __restrict__ words)
{
    int k = blockIdx.x * blockDim.x + threadIdx.x;
    if (k == 0) d_wcursor = 0;         // reset main-kernel cursor each replay
    if (k < NITEMS) {
        int r = __ldg(words + k);
        int pos = atomicAdd(&d_cnt[r], 1);
        if (pos < CAP) d_items[r * CAP + pos] = k;
    }
}

// ================= mbarrier / TMA helpers =================
__device__ __forceinline__ void mbar_init(uint32_t mbar, uint32_t count) {
    asm volatile("mbarrier.init.shared.b64 [%0], %1;" :: "r"(mbar), "r"(count) : "memory");
}
__device__ __forceinline__ void mbar_expect_tx(uint32_t mbar, uint32_t bytes) {
    asm volatile("mbarrier.arrive.expect_tx.shared.b64 _, [%0], %1;"
                 :: "r"(mbar), "r"(bytes) : "memory");
}
__device__ __forceinline__ void mbar_arrive(uint32_t mbar) {
    asm volatile("mbarrier.arrive.shared.b64 _, [%0];" :: "r"(mbar) : "memory");
}
__device__ __forceinline__ void bulk_copy_g2s(uint32_t dst_smem, const void* src,
                                              uint32_t bytes, uint32_t mbar) {
    asm volatile("cp.async.bulk.shared::cta.global.mbarrier::complete_tx::bytes "
                 "[%0], [%1], %2, [%3];"
                 :: "r"(dst_smem), "l"(src), "r"(bytes), "r"(mbar) : "memory");
}
__device__ __forceinline__ void mbar_wait(uint32_t mbar, uint32_t phase) {
    asm volatile(
        "{\n\t"
        ".reg .pred P;\n\t"
        "WAIT_%=:\n\t"
        "mbarrier.try_wait.parity.acquire.cta.shared::cta.b64 P, [%0], %1, 0x989680;\n\t"
        "@P bra DONE_%=;\n\t"
        "bra WAIT_%=;\n\t"
        "DONE_%=:\n\t"
        "}"
        :: "r"(mbar), "r"(phase) : "memory");
}

// ================= main kernel =================
__global__ __launch_bounds__(THREADS) void pair_gather_ws_kernel(
    const int* __restrict__ words,
    const float* __restrict__ W,
    const float* __restrict__ root,
    float* __restrict__ out)
{
    extern __shared__ float sbuf[];   // NSLOTS * V floats, then barriers
    __shared__ int s_mr[NSLOTS], s_mc[NSLOTS];
    __shared__ int s_items[NSLOTS][SITEMS];

    const int t = threadIdx.x;
    const uint32_t smem_base = (uint32_t)__cvta_generic_to_shared(sbuf);
    const uint32_t bar_base  = smem_base + NSLOTS * ROW_BYTES;
    // full[s] = bar_base + s*16, empty[s] = bar_base + s*16 + 8

    if (t == 0) {
        #pragma unroll
        for (int s0 = 0; s0 < NSLOTS; ++s0) {
            mbar_init(bar_base + s0 * 16, 1);       // full: producer arrives
            mbar_init(bar_base + s0 * 16 + 8, 1);   // empty: one consumer arrives
        }
    }
    __syncthreads();

    if (t >= CONSUMERS) {
        // ---------------- producer warp ----------------
        const int lane = t - CONSUMERS;
        const int q    = lane >> 3;      // row-within-chunk this lane serves
        const int idx  = lane & 7;       // item index this lane serves
        if (lane == 0)
            asm volatile("fence.proxy.async.shared::cta;" ::: "memory");
        __syncwarp();

        // prologue: grab first chunk, exchange counts, prefetch items
        int base;
        if (lane == 0) base = atomicAdd(&d_wcursor, CHUNK);
        base = __shfl_sync(0xFFFFFFFF, base, 0);
        int myc = 0;
        if (lane < CHUNK && base + lane < V) {
            myc = atomicExch(&d_cnt[base + lane], 0);   // read + reset
            if (myc > CAP) myc = CAP;
        }
        int cq = __shfl_sync(0xFFFFFFFF, myc, q);
        int myitem = 0;
        if (base + q < V && idx < cq && idx < SITEMS)
            myitem = __ldg(d_items + (size_t)(base + q) * CAP + idx);

        int k = 0;   // issued-slot counter (drives slot & phase)
        while (base < V) {
            // ---- prefetch next chunk (atomics + item LDGs issued early) ----
            int nbase;
            if (lane == 0) nbase = atomicAdd(&d_wcursor, CHUNK);
            nbase = __shfl_sync(0xFFFFFFFF, nbase, 0);
            int nc = 0;
            if (lane < CHUNK && nbase + lane < V) {
                nc = atomicExch(&d_cnt[nbase + lane], 0);
                if (nc > CAP) nc = CAP;
            }
            int ncq = __shfl_sync(0xFFFFFFFF, nc, q);
            int nitem = 0;
            if (nbase + q < V && idx < ncq && idx < SITEMS)
                nitem = __ldg(d_items + (size_t)(nbase + q) * CAP + idx);

            // ---- issue current chunk ----
            unsigned mask = __ballot_sync(0xFFFFFFFF, myc > 0);
            while (mask) {
                const int src = __ffs(mask) - 1;
                mask &= mask - 1;
                const int r = base + src;
                const int c = __shfl_sync(0xFFFFFFFF, myc, src);

                const int slot = k % NSLOTS;
                const int n    = k / NSLOTS;
                ++k;
                if (lane == 0)
                    mbar_wait(bar_base + slot * 16 + 8, (unsigned)((n & 1) ^ 1));
                __syncwarp();
                // deposit item list for this row into the slot
                if (q == src && idx < c && idx < SITEMS)
                    s_items[slot][idx] = myitem;
                if (lane == 0) {
                    s_mr[slot] = r;
                    s_mc[slot] = c;
                    mbar_expect_tx(bar_base + slot * 16, ROW_BYTES);
                    bulk_copy_g2s(smem_base + slot * ROW_BYTES,
                                  W + (size_t)r * V, ROW_BYTES,
                                  bar_base + slot * 16);
                }
            }

            base = nbase; myc = nc; myitem = nitem;
        }

        // sentinel
        if (lane == 0) {
            const int slot = k % NSLOTS;
            const int n    = k / NSLOTS;
            mbar_wait(bar_base + slot * 16 + 8, (unsigned)((n & 1) ^ 1));
            s_mr[slot] = -1;
            mbar_arrive(bar_base + slot * 16);
        }
    } else {
        // ---------------- consumer warps ----------------
        for (int k = 0;; ++k) {
            const int slot = k % NSLOTS;
            const int n    = k / NSLOTS;
            mbar_wait(bar_base + slot * 16, (unsigned)(n & 1));

            const int r = s_mr[slot];
            if (r < 0) break;
            const int c = s_mc[slot];
            const float rootv = __ldg(root + r);
            const float* __restrict__ row = sbuf + (size_t)slot * V;

            for (int it = 0; it < c; ++it) {
                const int blk = (it < SITEMS)
                              ? s_items[slot][it]
                              : __ldg(d_items + (size_t)r * CAP + it); // rare
                const int bb  = blk >> 11;
                const int i   = blk & (N_DIM - 1);
                const int4 cc = __ldg(reinterpret_cast<const int4*>(
                                         words + (size_t)bb * N_DIM) + t);
                const int j0 = t * 4;
                float4 v;
                v.x = row[cc.x];
                v.y = row[cc.y];
                v.z = row[cc.z];
                v.w = row[cc.w];
                const unsigned d = (unsigned)(i - j0);
                if (d < 4u) {
                    if      (d == 0u) v.x += rootv;
                    else if (d == 1u) v.y += rootv;
                    else if (d == 2u) v.z += rootv;
                    else              v.w += rootv;
                }
                *reinterpret_cast<float4*>(out + (size_t)blk * N_DIM + j0) = v;
            }

            asm volatile("bar.sync 1, %0;" :: "n"(CONSUMERS) : "memory");
            if (t == 0) mbar_arrive(bar_base + slot * 16 + 8);
        }
    }
}

// ================= launch =================
extern "C" void kernel_launch(void* const* d_in, const int* in_sizes, int n_in,
                              void* d_out, int out_size)
{
    const int*   words = (const int*)  d_in[0];
    const float* W     = (const float*)d_in[1];
    const float* root  = (const float*)d_in[2];
    float*       out   = (float*)d_out;

    static const size_t SMEM_DYN = (size_t)NSLOTS * ROW_BYTES + NSLOTS * 16;
    cudaFuncSetAttribute(pair_gather_ws_kernel,
                         cudaFuncAttributeMaxDynamicSharedMemorySize,
                         (int)SMEM_DYN);

    place_kernel<<<(NITEMS + 255) / 256, 256>>>(words);
    pair_gather_ws_kernel<<<GRID_MAIN, THREADS, SMEM_DYN>>>(words, W, root, out);
}

// round 10
// speedup vs baseline: 1.2840x; 1.0742x over previous
#include <cuda_runtime.h>
#include <cstdint>
#include <cstddef>

// out[b,i,j] = W[words[b,i], words[b,j]]  (+ root[words[b,i]] when i==j)
// V=10000, B=8, N=2048
//
// R10: R9 + split consumers into 2 groups of 8 warps that own alternating
// ring slots (overlaps consumer latency chains of adjacent slots) and
// replace the 512-thread bar.sync slot release with 8 warp-leader mbarrier
// arrivals (empty mbar count=8). Producer unchanged: 4-id cursor chunks,
// one-chunk-ahead prefetch of counts+items, 5-deep TMA ring of 40KB rows.

#define V 10000
#define B_DIM 8
#define N_DIM 2048
#define NITEMS (B_DIM * N_DIM)     // 16384
#define ROW_BYTES (V * 4)          // 40000
#define NSLOTS 5
#define CONSUMERS 512
#define GTHREADS 256               // threads per consumer group
#define GWARPS 8                   // warps per consumer group
#define THREADS (CONSUMERS + 32)
#define GRID_MAIN 152
#define CAP 64                     // bin capacity (actual max ~12)
#define CHUNK 4                    // vocab ids per cursor grab (2500 chunks)
#define SITEMS 8                   // items carried via smem per row

__device__ int d_cnt[V];           // zero-init; producer exchanges back to 0
__device__ int d_items[V * CAP];
__device__ int d_wcursor;          // reset by place_kernel

// ================= prepass: count + place =================
__global__ void place_kernel(const int* __restrict__ words)
{
    int k = blockIdx.x * blockDim.x + threadIdx.x;
    if (k == 0) d_wcursor = 0;         // reset main-kernel cursor each replay
    if (k < NITEMS) {
        int r = __ldg(words + k);
        int pos = atomicAdd(&d_cnt[r], 1);
        if (pos < CAP) d_items[r * CAP + pos] = k;
    }
}

// ================= mbarrier / TMA helpers =================
__device__ __forceinline__ void mbar_init(uint32_t mbar, uint32_t count) {
    asm volatile("mbarrier.init.shared.b64 [%0], %1;" :: "r"(mbar), "r"(count) : "memory");
}
__device__ __forceinline__ void mbar_expect_tx(uint32_t mbar, uint32_t bytes) {
    asm volatile("mbarrier.arrive.expect_tx.shared.b64 _, [%0], %1;"
                 :: "r"(mbar), "r"(bytes) : "memory");
}
__device__ __forceinline__ void mbar_arrive(uint32_t mbar) {
    asm volatile("mbarrier.arrive.shared.b64 _, [%0];" :: "r"(mbar) : "memory");
}
__device__ __forceinline__ void bulk_copy_g2s(uint32_t dst_smem, const void* src,
                                              uint32_t bytes, uint32_t mbar) {
    asm volatile("cp.async.bulk.shared::cta.global.mbarrier::complete_tx::bytes "
                 "[%0], [%1], %2, [%3];"
                 :: "r"(dst_smem), "l"(src), "r"(bytes), "r"(mbar) : "memory");
}
__device__ __forceinline__ void mbar_wait(uint32_t mbar, uint32_t phase) {
    asm volatile(
        "{\n\t"
        ".reg .pred P;\n\t"
        "WAIT_%=:\n\t"
        "mbarrier.try_wait.parity.acquire.cta.shared::cta.b64 P, [%0], %1, 0x989680;\n\t"
        "@P bra DONE_%=;\n\t"
        "bra WAIT_%=;\n\t"
        "DONE_%=:\n\t"
        "}"
        :: "r"(mbar), "r"(phase) : "memory");
}

// ================= main kernel =================
__global__ __launch_bounds__(THREADS) void pair_gather_ws_kernel(
    const int* __restrict__ words,
    const float* __restrict__ W,
    const float* __restrict__ root,
    float* __restrict__ out)
{
    extern __shared__ float sbuf[];   // NSLOTS * V floats, then barriers
    __shared__ int s_mr[NSLOTS], s_mc[NSLOTS];
    __shared__ int s_items[NSLOTS][SITEMS];

    const int t = threadIdx.x;
    const uint32_t smem_base = (uint32_t)__cvta_generic_to_shared(sbuf);
    const uint32_t bar_base  = smem_base + NSLOTS * ROW_BYTES;
    // full[s] = bar_base + s*16, empty[s] = bar_base + s*16 + 8

    if (t == 0) {
        #pragma unroll
        for (int s0 = 0; s0 < NSLOTS; ++s0) {
            mbar_init(bar_base + s0 * 16, 1);        // full: producer arrives
            mbar_init(bar_base + s0 * 16 + 8, GWARPS); // empty: 8 warp leaders
        }
    }
    __syncthreads();

    if (t >= CONSUMERS) {
        // ---------------- producer warp ----------------
        const int lane = t - CONSUMERS;
        const int q    = lane >> 3;      // row-within-chunk this lane serves
        const int idx  = lane & 7;       // item index this lane serves
        if (lane == 0)
            asm volatile("fence.proxy.async.shared::cta;" ::: "memory");
        __syncwarp();

        // prologue: grab first chunk, exchange counts, prefetch items
        int base;
        if (lane == 0) base = atomicAdd(&d_wcursor, CHUNK);
        base = __shfl_sync(0xFFFFFFFF, base, 0);
        int myc = 0;
        if (lane < CHUNK && base + lane < V) {
            myc = atomicExch(&d_cnt[base + lane], 0);   // read + reset
            if (myc > CAP) myc = CAP;
        }
        int cq = __shfl_sync(0xFFFFFFFF, myc, q);
        int myitem = 0;
        if (base + q < V && idx < cq && idx < SITEMS)
            myitem = __ldg(d_items + (size_t)(base + q) * CAP + idx);

        int k = 0;   // issued-slot counter (drives slot, phase, group)
        while (base < V) {
            // ---- prefetch next chunk (atomics + item LDGs issued early) ----
            int nbase;
            if (lane == 0) nbase = atomicAdd(&d_wcursor, CHUNK);
            nbase = __shfl_sync(0xFFFFFFFF, nbase, 0);
            int nc = 0;
            if (lane < CHUNK && nbase + lane < V) {
                nc = atomicExch(&d_cnt[nbase + lane], 0);
                if (nc > CAP) nc = CAP;
            }
            int ncq = __shfl_sync(0xFFFFFFFF, nc, q);
            int nitem = 0;
            if (nbase + q < V && idx < ncq && idx < SITEMS)
                nitem = __ldg(d_items + (size_t)(nbase + q) * CAP + idx);

            // ---- issue current chunk ----
            unsigned mask = __ballot_sync(0xFFFFFFFF, myc > 0);
            while (mask) {
                const int src = __ffs(mask) - 1;
                mask &= mask - 1;
                const int r = base + src;
                const int c = __shfl_sync(0xFFFFFFFF, myc, src);

                const int slot = k % NSLOTS;
                const int n    = k / NSLOTS;
                ++k;
                if (lane == 0)
                    mbar_wait(bar_base + slot * 16 + 8, (unsigned)((n & 1) ^ 1));
                __syncwarp();
                // deposit item list for this row into the slot
                if (q == src && idx < c && idx < SITEMS)
                    s_items[slot][idx] = myitem;
                __syncwarp();
                if (lane == 0) {
                    s_mr[slot] = r;
                    s_mc[slot] = c;
                    mbar_expect_tx(bar_base + slot * 16, ROW_BYTES);
                    bulk_copy_g2s(smem_base + slot * ROW_BYTES,
                                  W + (size_t)r * V, ROW_BYTES,
                                  bar_base + slot * 16);
                }
            }

            base = nbase; myc = nc; myitem = nitem;
        }

        // sentinels: one per consumer group (consecutive k covers both parities)
        if (lane == 0) {
            #pragma unroll
            for (int s2 = 0; s2 < 2; ++s2) {
                const int slot = k % NSLOTS;
                const int n    = k / NSLOTS;
                ++k;
                mbar_wait(bar_base + slot * 16 + 8, (unsigned)((n & 1) ^ 1));
                s_mr[slot] = -1;
                mbar_arrive(bar_base + slot * 16);
            }
        }
    } else {
        // ---------------- consumer warps (2 groups x 8 warps) ----------------
        const int g  = t / GTHREADS;       // group 0 or 1
        const int tg = t % GTHREADS;       // 0..255 within group

        for (int k = g;; k += 2) {
            const int slot = k % NSLOTS;
            const int n    = k / NSLOTS;
            mbar_wait(bar_base + slot * 16, (unsigned)(n & 1));

            const int r = s_mr[slot];
            if (r < 0) break;
            const int c = s_mc[slot];
            const float rootv = __ldg(root + r);
            const float* __restrict__ row = sbuf + (size_t)slot * V;

            for (int it = 0; it < c; ++it) {
                const int blk = (it < SITEMS)
                              ? s_items[slot][it]
                              : __ldg(d_items + (size_t)r * CAP + it); // rare
                const int bb  = blk >> 11;
                const int i   = blk & (N_DIM - 1);
                const int4* __restrict__ wb4 =
                    reinterpret_cast<const int4*>(words + (size_t)bb * N_DIM);
                const int j0 = tg * 8;
                const int4 c0 = __ldg(wb4 + tg * 2);
                const int4 c1 = __ldg(wb4 + tg * 2 + 1);
                float4 v0, v1;
                v0.x = row[c0.x]; v0.y = row[c0.y];
                v0.z = row[c0.z]; v0.w = row[c0.w];
                v1.x = row[c1.x]; v1.y = row[c1.y];
                v1.z = row[c1.z]; v1.w = row[c1.w];
                const unsigned d = (unsigned)(i - j0);
                if (d < 8u) {
                    if      (d == 0u) v0.x += rootv;
                    else if (d == 1u) v0.y += rootv;
                    else if (d == 2u) v0.z += rootv;
                    else if (d == 3u) v0.w += rootv;
                    else if (d == 4u) v1.x += rootv;
                    else if (d == 5u) v1.y += rootv;
                    else if (d == 6u) v1.z += rootv;
                    else              v1.w += rootv;
                }
                float* __restrict__ orow = out + (size_t)blk * N_DIM + j0;
                *reinterpret_cast<float4*>(orow)     = v0;
                *reinterpret_cast<float4*>(orow + 4) = v1;
            }

            // this warp is done reading the slot: warp-leader arrive (count=8)
            __syncwarp();
            if ((tg & 31) == 0) mbar_arrive(bar_base + slot * 16 + 8);
        }
    }
}

// ================= launch =================
extern "C" void kernel_launch(void* const* d_in, const int* in_sizes, int n_in,
                              void* d_out, int out_size)
{
    const int*   words = (const int*)  d_in[0];
    const float* W     = (const float*)d_in[1];
    const float* root  = (const float*)d_in[2];
    float*       out   = (float*)d_out;

    static const size_t SMEM_DYN = (size_t)NSLOTS * ROW_BYTES + NSLOTS * 16;
    cudaFuncSetAttribute(pair_gather_ws_kernel,
                         cudaFuncAttributeMaxDynamicSharedMemorySize,
                         (int)SMEM_DYN);

    place_kernel<<<(NITEMS + 255) / 256, 256>>>(words);
    pair_gather_ws_kernel<<<GRID_MAIN, THREADS, SMEM_DYN>>>(words, W, root, out);
}